// round 1
// baseline (speedup 1.0000x reference)
#include <cuda_runtime.h>
#include <math.h>
#include <stdint.h>

#define B_  128
#define C_  1024
#define H_  24
#define W_  24
#define N_  576          // H*W
#define NH  8
#define HD  128          // C/NH
#define QH  12
#define QW  12
#define QN  144          // QH*QW

// ---------------- scratch (static device allocations; allowed) ----------------
__device__ float g_xt  [(size_t)B_*N_*C_];     // [B,N,C]   302 MB
__device__ float g_xp  [(size_t)B_*QN*C_];     // [B,qN,C]   75 MB
__device__ float g_q   [(size_t)B_*QN*C_];     // [B,qN,C]   75 MB
__device__ float g_k   [(size_t)B_*N_*C_];     // [B,N,C]   302 MB
__device__ float g_v   [(size_t)B_*N_*C_];     // [B,N,C]   302 MB
__device__ float g_attn[(size_t)B_*NH*QN*N_];  // [BH,qN,N] 340 MB
__device__ float g_relh[(size_t)B_*NH*QN*H_];  // [BH,qN,24]
__device__ float g_relw[(size_t)B_*NH*QN*W_];  // [BH,qN,24]
__device__ float g_o   [(size_t)B_*QN*C_];     // [B,qN,C]   75 MB

// ---------------- 1) transpose x[B,C,N] -> xt[B,N,C] ----------------
__global__ __launch_bounds__(256) void transpose_kernel(const float* __restrict__ x) {
    __shared__ float tile[32][33];
    int b  = blockIdx.z;
    int n0 = blockIdx.x * 32;   // over N (576/32 = 18)
    int c0 = blockIdx.y * 32;   // over C (1024/32 = 32)
    int tx = threadIdx.x, ty = threadIdx.y;  // (32, 8)
    const float* xb = x + (size_t)b * C_ * N_;
    #pragma unroll
    for (int i = 0; i < 4; i++) {
        int c = c0 + ty + i * 8;
        tile[ty + i * 8][tx] = xb[(size_t)c * N_ + n0 + tx];
    }
    __syncthreads();
    float* xt = g_xt + (size_t)b * N_ * C_;
    #pragma unroll
    for (int i = 0; i < 4; i++) {
        int n = n0 + ty + i * 8;
        xt[(size_t)n * C_ + c0 + tx] = tile[tx][ty + i * 8];
    }
}

// ---------------- 2) avg-pool 3x3 s2 pad1 (count_include_pad) -> xp[B,qN,C] ----------------
__global__ __launch_bounds__(256) void pool_kernel(const float* __restrict__ x) {
    __shared__ float sp[16][577];   // [c_local][spatial], padded stride
    int b  = blockIdx.y;
    int c0 = blockIdx.x * 16;
    int tid = threadIdx.x;
    const float* xb = x + (size_t)b * C_ * N_ + (size_t)c0 * N_;
    #pragma unroll
    for (int r = 0; r < 36; r++) {          // 16*576/256 = 36
        int idx = tid + r * 256;
        int p = idx / 576, n = idx - p * 576;
        sp[p][n] = xb[(size_t)p * N_ + n];
    }
    __syncthreads();
    #pragma unroll
    for (int r = 0; r < 9; r++) {           // 144*16/256 = 9
        int idx = tid + r * 256;
        int qn = idx >> 4, cl = idx & 15;
        int qy = qn / 12, qx = qn - qy * 12;
        float s = 0.f;
        #pragma unroll
        for (int dy = -1; dy <= 1; dy++) {
            int y = 2 * qy + dy;
            if ((unsigned)y < 24u) {
                #pragma unroll
                for (int dx = -1; dx <= 1; dx++) {
                    int xx = 2 * qx + dx;
                    if ((unsigned)xx < 24u) s += sp[cl][y * 24 + xx];
                }
            }
        }
        g_xp[((size_t)b * QN + qn) * C_ + c0 + cl] = s * (1.0f / 9.0f);
    }
}

// ---------------- 3) generic GEMM C = A[M,K] @ B[K,N] (+ bias / NCHW scatter) ----------------
// mode 0: C[m,n] row-major.  mode 1: out[b, n, m%QN] with bias (final projection)
__global__ __launch_bounds__(256) void gemm128(const float* __restrict__ A,
                                               const float* __restrict__ Bm,
                                               const float* __restrict__ bias,
                                               float* __restrict__ Cm,
                                               int M, int N, int K, int mode) {
    __shared__ float As[8][128];  // transposed: As[k][m]
    __shared__ float Bs[8][128];
    int tid = threadIdx.x;
    int rowBase = blockIdx.y * 128;
    int colBase = blockIdx.x * 128;
    int aRow = tid >> 1;
    int aK   = (tid & 1) * 4;
    int bK   = tid >> 5;
    int bCol = (tid & 31) * 4;
    const float* Ap = A  + (size_t)(rowBase + aRow) * K + aK;
    const float* Bp = Bm + (size_t)bK * N + colBase + bCol;
    int ty = tid >> 4, tx = tid & 15;
    float acc[8][8];
    #pragma unroll
    for (int i = 0; i < 8; i++)
        #pragma unroll
        for (int j = 0; j < 8; j++) acc[i][j] = 0.f;

    for (int k0 = 0; k0 < K; k0 += 8) {
        float4 a4 = *(const float4*)(Ap + k0);
        float4 b4 = *(const float4*)(Bp + (size_t)k0 * N);
        As[aK + 0][aRow] = a4.x;
        As[aK + 1][aRow] = a4.y;
        As[aK + 2][aRow] = a4.z;
        As[aK + 3][aRow] = a4.w;
        *(float4*)&Bs[bK][bCol] = b4;
        __syncthreads();
        #pragma unroll
        for (int k = 0; k < 8; k++) {
            float ar[8], br[8];
            *(float4*)&ar[0] = *(const float4*)&As[k][ty * 8];
            *(float4*)&ar[4] = *(const float4*)&As[k][ty * 8 + 4];
            *(float4*)&br[0] = *(const float4*)&Bs[k][tx * 8];
            *(float4*)&br[4] = *(const float4*)&Bs[k][tx * 8 + 4];
            #pragma unroll
            for (int i = 0; i < 8; i++)
                #pragma unroll
                for (int j = 0; j < 8; j++)
                    acc[i][j] += ar[i] * br[j];
        }
        __syncthreads();
    }

    if (mode == 0) {
        #pragma unroll
        for (int i = 0; i < 8; i++) {
            int row = rowBase + ty * 8 + i;
            float* cp = Cm + (size_t)row * N + colBase + tx * 8;
            *(float4*)(cp + 0) = make_float4(acc[i][0], acc[i][1], acc[i][2], acc[i][3]);
            *(float4*)(cp + 4) = make_float4(acc[i][4], acc[i][5], acc[i][6], acc[i][7]);
        }
    } else {
        #pragma unroll
        for (int i = 0; i < 8; i++) {
            int row = rowBase + ty * 8 + i;
            int bq = row / QN, qi = row - bq * QN;
            #pragma unroll
            for (int j = 0; j < 8; j++) {
                int col = colBase + tx * 8 + j;
                Cm[((size_t)bq * C_ + col) * QN + qi] = acc[i][j] + bias[col];
            }
        }
    }
}

// ---------------- 4) relative position bias dots ----------------
// rh[bh,i,ky] = dot(q[bh,i,:], rel_pos_h[2*qy-ky+23, :]);  rw analogous
__global__ __launch_bounds__(64) void relpos_kernel(const float* __restrict__ rel_h,
                                                    const float* __restrict__ rel_w) {
    int gid = blockIdx.x;              // bh*QN + i
    int bh = gid / QN, i = gid - bh * QN;
    int b = bh >> 3, h = bh & 7;
    int qy = i / 12, qx = i - qy * 12;
    int t = threadIdx.x;
    const float* qrow = g_q + ((size_t)b * QN + i) * C_ + h * HD;
    if (t < 24) {
        const float* R = rel_h + (size_t)(2 * qy - t + 23) * HD;
        float a0 = 0, a1 = 0, a2 = 0, a3 = 0;
        #pragma unroll
        for (int d = 0; d < HD; d += 4) {
            a0 += qrow[d + 0] * R[d + 0];
            a1 += qrow[d + 1] * R[d + 1];
            a2 += qrow[d + 2] * R[d + 2];
            a3 += qrow[d + 3] * R[d + 3];
        }
        g_relh[(size_t)gid * 24 + t] = (a0 + a1) + (a2 + a3);
    } else if (t >= 32 && t < 56) {
        int kx = t - 32;
        const float* R = rel_w + (size_t)(2 * qx - kx + 23) * HD;
        float a0 = 0, a1 = 0, a2 = 0, a3 = 0;
        #pragma unroll
        for (int d = 0; d < HD; d += 4) {
            a0 += qrow[d + 0] * R[d + 0];
            a1 += qrow[d + 1] * R[d + 1];
            a2 += qrow[d + 2] * R[d + 2];
            a3 += qrow[d + 3] * R[d + 3];
        }
        g_relw[(size_t)gid * 24 + kx] = (a0 + a1) + (a2 + a3);
    }
}

// ---------------- 5) attn logits: scale*q@k^T + rel_h + rel_w ----------------
// per (b,h): [144,128] @ [576,128]^T ; tile 48x64, thread 3x4
__global__ __launch_bounds__(256) void qk_kernel() {
    __shared__ float Qs[64][49];   // [k][row]
    __shared__ float Ks[64][68];   // [k][col]
    int bh = blockIdx.z;
    int b = bh >> 3, h = bh & 7;
    int rowBase = blockIdx.y * 48;
    int colBase = blockIdx.x * 64;
    int tid = threadIdx.x;
    int tx = tid & 15, ty = tid >> 4;
    const float* qbase = g_q + ((size_t)b * QN + rowBase) * C_ + h * HD;
    const float* kbase = g_k + ((size_t)b * N_ + colBase) * C_ + h * HD;
    float acc[3][4] = {{0.f}};

    for (int kc = 0; kc < HD; kc += 64) {
        #pragma unroll
        for (int r = 0; r < 3; r++) {          // 48*64/4/256 = 3
            int f4i = tid + 256 * r;
            int row = f4i >> 4;
            int kk = (f4i & 15) * 4;
            float4 vv = *(const float4*)(qbase + (size_t)row * C_ + kc + kk);
            Qs[kk + 0][row] = vv.x; Qs[kk + 1][row] = vv.y;
            Qs[kk + 2][row] = vv.z; Qs[kk + 3][row] = vv.w;
        }
        #pragma unroll
        for (int r = 0; r < 4; r++) {          // 64*64/4/256 = 4
            int f4i = tid + 256 * r;
            int col = f4i >> 4;
            int kk = (f4i & 15) * 4;
            float4 vv = *(const float4*)(kbase + (size_t)col * C_ + kc + kk);
            Ks[kk + 0][col] = vv.x; Ks[kk + 1][col] = vv.y;
            Ks[kk + 2][col] = vv.z; Ks[kk + 3][col] = vv.w;
        }
        __syncthreads();
        #pragma unroll 8
        for (int kk = 0; kk < 64; kk++) {
            float4 bv = *(const float4*)&Ks[kk][tx * 4];
            float a0 = Qs[kk][ty * 3 + 0];
            float a1 = Qs[kk][ty * 3 + 1];
            float a2 = Qs[kk][ty * 3 + 2];
            acc[0][0] += a0 * bv.x; acc[0][1] += a0 * bv.y; acc[0][2] += a0 * bv.z; acc[0][3] += a0 * bv.w;
            acc[1][0] += a1 * bv.x; acc[1][1] += a1 * bv.y; acc[1][2] += a1 * bv.z; acc[1][3] += a1 * bv.w;
            acc[2][0] += a2 * bv.x; acc[2][1] += a2 * bv.y; acc[2][2] += a2 * bv.z; acc[2][3] += a2 * bv.w;
        }
        __syncthreads();
    }

    const float scale = 0.08838834764831845f;   // 128^-0.5
    #pragma unroll
    for (int m = 0; m < 3; m++) {
        int i = rowBase + ty * 3 + m;
        const float* rh = g_relh + ((size_t)bh * QN + i) * 24;
        const float* rw = g_relw + ((size_t)bh * QN + i) * 24;
        float* sp = g_attn + ((size_t)bh * QN + i) * N_ + colBase + tx * 4;
        #pragma unroll
        for (int j = 0; j < 4; j++) {
            int jj = colBase + tx * 4 + j;
            int ky = jj / 24, kx = jj - ky * 24;
            sp[j] = acc[m][j] * scale + rh[ky] + rw[kx];
        }
    }
}

// ---------------- 6) softmax over last dim (576) ----------------
__global__ __launch_bounds__(192) void softmax_kernel() {
    __shared__ float sm[6], ss[6];
    size_t row = blockIdx.x;
    float* p = g_attn + row * (size_t)N_;
    int t = threadIdx.x;
    float v0 = p[t], v1 = p[t + 192], v2 = p[t + 384];
    float m = fmaxf(v0, fmaxf(v1, v2));
    #pragma unroll
    for (int o = 16; o > 0; o >>= 1) m = fmaxf(m, __shfl_xor_sync(0xffffffffu, m, o));
    if ((t & 31) == 0) sm[t >> 5] = m;
    __syncthreads();
    float mm = fmaxf(fmaxf(fmaxf(sm[0], sm[1]), fmaxf(sm[2], sm[3])), fmaxf(sm[4], sm[5]));
    float e0 = __expf(v0 - mm), e1 = __expf(v1 - mm), e2 = __expf(v2 - mm);
    float s = e0 + e1 + e2;
    #pragma unroll
    for (int o = 16; o > 0; o >>= 1) s += __shfl_xor_sync(0xffffffffu, s, o);
    if ((t & 31) == 0) ss[t >> 5] = s;
    __syncthreads();
    float tot = (ss[0] + ss[1]) + (ss[2] + ss[3]) + (ss[4] + ss[5]);
    float inv = 1.0f / tot;
    p[t] = e0 * inv; p[t + 192] = e1 * inv; p[t + 384] = e2 * inv;
}

// ---------------- 7) out = attn @ v + q  (per b,h: [144,576]@[576,128]) ----------------
__global__ __launch_bounds__(256) void av_kernel() {
    __shared__ float Ps[48][33];
    __shared__ float Vs[32][68];
    int bh = blockIdx.z;
    int b = bh >> 3, h = bh & 7;
    int rowBase = blockIdx.y * 48;
    int colBase = blockIdx.x * 64;
    int tid = threadIdx.x;
    int tx = tid & 15, ty = tid >> 4;
    const float* pbase = g_attn + ((size_t)bh * QN + rowBase) * N_;
    const float* vbase = g_v + (size_t)b * N_ * C_ + h * HD + colBase;
    float acc[3][4] = {{0.f}};

    for (int k0 = 0; k0 < N_; k0 += 32) {
        #pragma unroll
        for (int r = 0; r < 6; r++) {          // 48*32/256 = 6
            int idx = tid + 256 * r;
            int row = idx >> 5, kk = idx & 31;
            Ps[row][kk] = pbase[(size_t)row * N_ + k0 + kk];
        }
        #pragma unroll
        for (int r = 0; r < 2; r++) {          // 32*64/4/256 = 2
            int f4i = tid + 256 * r;
            int vrow = f4i >> 4, col = (f4i & 15) * 4;
            float4 vv = *(const float4*)(vbase + (size_t)(k0 + vrow) * C_ + col);
            *(float4*)&Vs[vrow][col] = vv;
        }
        __syncthreads();
        #pragma unroll 8
        for (int kk = 0; kk < 32; kk++) {
            float4 bv = *(const float4*)&Vs[kk][tx * 4];
            float a0 = Ps[ty * 3 + 0][kk];
            float a1 = Ps[ty * 3 + 1][kk];
            float a2 = Ps[ty * 3 + 2][kk];
            acc[0][0] += a0 * bv.x; acc[0][1] += a0 * bv.y; acc[0][2] += a0 * bv.z; acc[0][3] += a0 * bv.w;
            acc[1][0] += a1 * bv.x; acc[1][1] += a1 * bv.y; acc[1][2] += a1 * bv.z; acc[1][3] += a1 * bv.w;
            acc[2][0] += a2 * bv.x; acc[2][1] += a2 * bv.y; acc[2][2] += a2 * bv.z; acc[2][3] += a2 * bv.w;
        }
        __syncthreads();
    }

    #pragma unroll
    for (int m = 0; m < 3; m++) {
        int i = rowBase + ty * 3 + m;
        size_t off = ((size_t)b * QN + i) * C_ + h * HD + colBase + tx * 4;
        const float* qp = g_q + off;
        float* op = g_o + off;
        #pragma unroll
        for (int j = 0; j < 4; j++) op[j] = acc[m][j] + qp[j];
    }
}

// ---------------- launch ----------------
extern "C" void kernel_launch(void* const* d_in, const int* in_sizes, int n_in,
                              void* d_out, int out_size) {
    const float* x   = (const float*)d_in[0];
    const float* Wq  = (const float*)d_in[1];
    const float* Wk  = (const float*)d_in[2];
    const float* Wv  = (const float*)d_in[3];
    const float* Wp  = (const float*)d_in[4];
    const float* bp  = (const float*)d_in[5];
    const float* rph = (const float*)d_in[6];
    const float* rpw = (const float*)d_in[7];
    float* out = (float*)d_out;

    float *xt, *xp, *q, *k, *v, *o;
    cudaGetSymbolAddress((void**)&xt, g_xt);
    cudaGetSymbolAddress((void**)&xp, g_xp);
    cudaGetSymbolAddress((void**)&q,  g_q);
    cudaGetSymbolAddress((void**)&k,  g_k);
    cudaGetSymbolAddress((void**)&v,  g_v);
    cudaGetSymbolAddress((void**)&o,  g_o);

    transpose_kernel<<<dim3(18, 32, B_), dim3(32, 8)>>>(x);
    pool_kernel<<<dim3(C_ / 16, B_), 256>>>(x);

    gemm128<<<dim3(C_ / 128, (B_ * N_) / 128), 256>>>(xt, Wk, nullptr, k, B_ * N_, C_, C_, 0);
    gemm128<<<dim3(C_ / 128, (B_ * N_) / 128), 256>>>(xt, Wv, nullptr, v, B_ * N_, C_, C_, 0);
    gemm128<<<dim3(C_ / 128, (B_ * QN) / 128), 256>>>(xp, Wq, nullptr, q, B_ * QN, C_, C_, 0);

    relpos_kernel<<<B_ * NH * QN, 64>>>(rph, rpw);
    qk_kernel<<<dim3(N_ / 64, QN / 48, B_ * NH), 256>>>();
    softmax_kernel<<<B_ * NH * QN, 192>>>();
    av_kernel<<<dim3(HD / 64, QN / 48, B_ * NH), 256>>>();

    gemm128<<<dim3(C_ / 128, (B_ * QN) / 128), 256>>>(o, Wp, bp, out, B_ * QN, C_, C_, 1);
}